// round 15
// baseline (speedup 1.0000x reference)
#include <cuda_runtime.h>
#include <cstdint>

#define Bq 32
#define Nn 64
#define Hh 128
#define Cc 16
#define SIGMA 0.5f
#define PAD 68
#define TTS 132
#define SMAX 256

typedef unsigned long long ull;

#define NB64()  asm volatile("bar.sync 1, 64;" ::: "memory")

__device__ __forceinline__ ull ffma2(ull a, ull b, ull c) {
    ull d;
    asm("fma.rn.f32x2 %0, %1, %2, %3;" : "=l"(d) : "l"(a), "l"(b), "l"(c));
    return d;
}
__device__ __forceinline__ ull pack2(float x, float y) {
    ull d;
    asm("mov.b64 %0, {%1, %2};" : "=l"(d) : "f"(x), "f"(y));
    return d;
}
__device__ __forceinline__ float lo2(ull v) { return __uint_as_float((unsigned)v); }
__device__ __forceinline__ float hi2(ull v) { return __uint_as_float((unsigned)(v >> 32)); }

// ---------------- device scratch ----------------
__device__ int g_concepts[SMAX * Bq * Nn];
__device__ unsigned long long g_adjbits[Bq * Nn];
__device__ unsigned long long g_maskbits[Bq];
__device__ int g_maxcl[Bq];
__device__ int g_qhead;

// ====== kernel 1: zero accumulators + queue ======
__global__ void zero_kernel(float* out, int n) {
    for (int i = blockIdx.x * blockDim.x + threadIdx.x; i < n;
         i += gridDim.x * blockDim.x)
        out[i] = 0.f;
    if (blockIdx.x == 0 && threadIdx.x < Bq) g_maxcl[threadIdx.x] = 0;
    if (blockIdx.x == 0 && threadIdx.x == 0) g_qhead = 0;
}

// ====== kernel 2: full GCN stack, one block per batch ======
// phases: prep -> h1=x@W1 -> xe=relu(A@h1+b1)*mask -> h2=xe@W2 ->
//         x_emb=relu(A@h2+b2)*mask
struct SmemG {
    union {
        float xs[Hh * PAD];   // x transposed (phase B input)
        float xet[Hh * PAD];  // xe transposed (phase D input)
    } u;                      // 34816 B
    float hbuf[Nn * Hh];      // h1 then h2, [row][ho]   32768 B
    float anorm[Nn * Nn];     // symmetric -> serves transposed reads  16384 B
    float deg[Nn];
};  // ~84.2 KB

__global__ __launch_bounds__(256) void gcn_all(
    const float* __restrict__ x, const float* __restrict__ adj,
    const void* maskp, const float* __restrict__ W1,
    const float* __restrict__ b1, const float* __restrict__ W2,
    const float* __restrict__ b2, float* __restrict__ xemb_out) {
    extern __shared__ char smemraw[];
    SmemG* sm = (SmemG*)smemraw;
    int b = blockIdx.x, tid = threadIdx.x;

    // ---- phase A: prep ----
    if (tid == 0) {
        unsigned first = ((const unsigned*)maskp)[0];
        int mode = (first == 1u) ? 1 : ((first == 0x3F800000u) ? 2 : 0);
        unsigned long long bits = 0;
        for (int j = 0; j < Nn; j++) {
            bool m;
            if (mode == 0)      m = ((const unsigned char*)maskp)[b * Nn + j] != 0;
            else if (mode == 1) m = ((const int*)maskp)[b * Nn + j] != 0;
            else                m = ((const float*)maskp)[b * Nn + j] != 0.f;
            if (m) bits |= 1ull << j;
        }
        g_maskbits[b] = bits;
    }
    if (tid < Nn) {
        float s = 0.f;
        unsigned long long abits = 0;
        const float* arow = adj + (size_t)b * Nn * Nn + (size_t)tid * Nn;
        for (int j = 0; j < Nn; j++) {
            float v = arow[j];
            if (v > 0.f) abits |= 1ull << j;
            s += (j == tid) ? 1.f : v;
        }
        g_adjbits[b * Nn + tid] = abits;
        sm->deg[tid] = rsqrtf(fmaxf(s, 1.f));
    }
    for (int idx = tid; idx < Nn * Hh; idx += 256) {
        int i = idx >> 7, h = idx & 127;
        sm->u.xs[h * PAD + i] = x[(size_t)b * Nn * Hh + idx];
    }
    __syncthreads();
    for (int idx = tid; idx < Nn * Nn; idx += 256) {
        int i = idx >> 6, j = idx & 63;
        float a = (i == j) ? 1.f : adj[(size_t)b * Nn * Nn + idx];
        sm->anorm[idx] = sm->deg[i] * a * sm->deg[j];
    }

    int ho = tid & 127, rg = tid >> 7;

    // ---- phase B: h1 = x @ W1 -> hbuf ----
    {
        int r0 = rg * 32;
        ull acc2[16];
#pragma unroll
        for (int p = 0; p < 16; p++) acc2[p] = 0ull;
#pragma unroll 4
        for (int k = 0; k < Hh; k++) {
            float w = W1[k * Hh + ho];
            ull ww = pack2(w, w);
            const ulonglong2* xr = (const ulonglong2*)(sm->u.xs + k * PAD + r0);
#pragma unroll
            for (int q = 0; q < 8; q++) {
                ulonglong2 p0 = xr[q];
                acc2[q * 2 + 0] = ffma2(p0.x, ww, acc2[q * 2 + 0]);
                acc2[q * 2 + 1] = ffma2(p0.y, ww, acc2[q * 2 + 1]);
            }
        }
#pragma unroll
        for (int p = 0; p < 16; p++) {
            sm->hbuf[(r0 + 2 * p + 0) * Hh + ho] = lo2(acc2[p]);
            sm->hbuf[(r0 + 2 * p + 1) * Hh + ho] = hi2(acc2[p]);
        }
    }
    __syncthreads();  // hbuf(h1), anorm ready; xs dead after this phase

    unsigned long long mb = g_maskbits[b];

    // ---- phase C: xe = relu(A@h1 + b1) * mask -> xet (overlays xs) ----
    {
        float bv = b1[ho];
#pragma unroll
        for (int r0 = 0; r0 < Nn; r0 += 32) {
            int i0 = r0 + rg * 16;
            float acc[16];
#pragma unroll
            for (int q = 0; q < 16; q++) acc[q] = bv;
#pragma unroll 2
            for (int j = 0; j < Nn; j++) {
                float hv = sm->hbuf[j * Hh + ho];
                const float4* ar = (const float4*)(sm->anorm + j * Nn + i0);
#pragma unroll
                for (int q = 0; q < 4; q++) {
                    float4 v = ar[q];
                    acc[q * 4 + 0] += v.x * hv;
                    acc[q * 4 + 1] += v.y * hv;
                    acc[q * 4 + 2] += v.z * hv;
                    acc[q * 4 + 3] += v.w * hv;
                }
            }
#pragma unroll
            for (int q = 0; q < 16; q++) {
                int i = i0 + q;
                float v = ((mb >> i) & 1ull) ? fmaxf(acc[q], 0.f) : 0.f;
                sm->u.xet[ho * PAD + i] = v;
            }
        }
    }
    __syncthreads();  // xet ready; hbuf(h1) reads done

    // ---- phase D: h2 = xe @ W2 -> hbuf ----
    {
        int r0 = rg * 32;
        ull acc2[16];
#pragma unroll
        for (int p = 0; p < 16; p++) acc2[p] = 0ull;
#pragma unroll 4
        for (int k = 0; k < Hh; k++) {
            float w = W2[k * Hh + ho];
            ull ww = pack2(w, w);
            const ulonglong2* xr = (const ulonglong2*)(sm->u.xet + k * PAD + r0);
#pragma unroll
            for (int q = 0; q < 8; q++) {
                ulonglong2 p0 = xr[q];
                acc2[q * 2 + 0] = ffma2(p0.x, ww, acc2[q * 2 + 0]);
                acc2[q * 2 + 1] = ffma2(p0.y, ww, acc2[q * 2 + 1]);
            }
        }
        __syncthreads();  // h1 reads in C already done; guard hbuf overwrite
#pragma unroll
        for (int p = 0; p < 16; p++) {
            sm->hbuf[(r0 + 2 * p + 0) * Hh + ho] = lo2(acc2[p]);
            sm->hbuf[(r0 + 2 * p + 1) * Hh + ho] = hi2(acc2[p]);
        }
    }
    __syncthreads();  // hbuf(h2) ready

    // ---- phase E: x_emb = relu(A@h2 + b2) * mask -> global ----
    {
        float bv = b2[ho];
#pragma unroll
        for (int r0 = 0; r0 < Nn; r0 += 32) {
            int i0 = r0 + rg * 16;
            float acc[16];
#pragma unroll
            for (int q = 0; q < 16; q++) acc[q] = bv;
#pragma unroll 2
            for (int j = 0; j < Nn; j++) {
                float hv = sm->hbuf[j * Hh + ho];
                const float4* ar = (const float4*)(sm->anorm + j * Nn + i0);
#pragma unroll
                for (int q = 0; q < 4; q++) {
                    float4 v = ar[q];
                    acc[q * 4 + 0] += v.x * hv;
                    acc[q * 4 + 1] += v.y * hv;
                    acc[q * 4 + 2] += v.z * hv;
                    acc[q * 4 + 3] += v.w * hv;
                }
            }
#pragma unroll
            for (int q = 0; q < 16; q++) {
                int i = i0 + q;
                float v = ((mb >> i) & 1ull) ? fmaxf(acc[q], 0.f) : 0.f;
                xemb_out[((size_t)b * Nn + i) * Hh + ho] = v;
            }
        }
    }
}

// ====== kernel 3: MLP + argmax — R10 body + work-queue balancing ======
struct SmemA {
    union {
        float xa[Hh * PAD];                      // 34816 B
        struct {
            float tt2[32 * TTS];                 // 16896 B
            float lg[Nn * Cc];                   // 4096 B
        } ph2;
    } u;
    float cwbuf[32 * Hh];                        // 16384 B
    int job;
};  // ~51.2 KB -> 4 blocks/SM

__global__ __launch_bounds__(256, 4) void mlp_kernel(
    const float* __restrict__ xemb, const float* __restrict__ noise,
    const float* __restrict__ cW1, const float* __restrict__ cb1,
    const float* __restrict__ cW2, const float* __restrict__ cb2,
    int total) {
    extern __shared__ char smemraw[];
    SmemA* sm = (SmemA*)smemraw;
    int tid = threadIdx.x;

    int hoq = tid & 31, ng = tid >> 5;
    int myP = ng >> 2;
    int lnbase = (ng & 3) * 8;
    float4 bv1 = *(const float4*)(cb1 + hoq * 4);
    const float* bp1 = (const float*)&bv1;
    float cb2a = cb2[(tid >> 5) * 2 + 0];
    float cb2b = cb2[(tid >> 5) * 2 + 1];

    for (;;) {
        if (tid == 0) sm->job = atomicAdd(&g_qhead, 1);
        __syncthreads();
        int job = sm->job;
        if (job >= total) break;
        int b = job & (Bq - 1);
        int bs = job;  // job = s*Bq + b layout: s = job >> 5
        const float* xb = xemb + (size_t)b * Nn * Hh;
        const float* nz = noise + (size_t)bs * Nn * Hh;
#pragma unroll 4
        for (int idx = tid; idx < Nn * Hh; idx += 256) {
            int i = idx >> 7, h = idx & 127;
            sm->u.xa[h * PAD + i] = xb[idx] + SIGMA * nz[idx];
        }

        ull acc[4][4];
#pragma unroll
        for (int j = 0; j < 4; j++) {
            ull bi = pack2(bp1[j], bp1[j]);
#pragma unroll
            for (int np = 0; np < 4; np++) acc[j][np] = bi;
        }

        for (int kc = 0; kc < 4; kc++) {
            {
                const float4* src = (const float4*)(cW1 + kc * 32 * Hh);
                float4* dst4 = (float4*)sm->cwbuf;
#pragma unroll
                for (int q = 0; q < 4; q++) dst4[tid + 256 * q] = src[tid + 256 * q];
            }
            __syncthreads();
#pragma unroll 2
            for (int kk = 0; kk < 32; kk++) {
                int k = kc * 32 + kk;
                const ulonglong2* xr =
                    (const ulonglong2*)(sm->u.xa + k * PAD + ng * 8);
                ulonglong2 xA = xr[0];
                ulonglong2 xB = xr[1];
                float4 wv = *(const float4*)(sm->cwbuf + kk * Hh + hoq * 4);
                const float* wp = (const float*)&wv;
#pragma unroll
                for (int j = 0; j < 4; j++) {
                    ull wb = pack2(wp[j], wp[j]);
                    acc[j][0] = ffma2(xA.x, wb, acc[j][0]);
                    acc[j][1] = ffma2(xA.y, wb, acc[j][1]);
                    acc[j][2] = ffma2(xB.x, wb, acc[j][2]);
                    acc[j][3] = ffma2(xB.y, wb, acc[j][3]);
                }
            }
            __syncthreads();
        }

        {
            const float4* src = (const float4*)cW2;
            float4* dst4 = (float4*)sm->cwbuf;
            dst4[tid] = src[tid];
            dst4[tid + 256] = src[tid + 256];
        }

#pragma unroll
        for (int P = 0; P < 2; P++) {
            if (myP == P) {
#pragma unroll
                for (int nn = 0; nn < 8; nn++) {
                    int np = nn >> 1;
                    float4 v;
                    if (nn & 1) {
                        v.x = hi2(acc[0][np]); v.y = hi2(acc[1][np]);
                        v.z = hi2(acc[2][np]); v.w = hi2(acc[3][np]);
                    } else {
                        v.x = lo2(acc[0][np]); v.y = lo2(acc[1][np]);
                        v.z = lo2(acc[2][np]); v.w = lo2(acc[3][np]);
                    }
                    v.x = fmaxf(v.x, 0.f); v.y = fmaxf(v.y, 0.f);
                    v.z = fmaxf(v.z, 0.f); v.w = fmaxf(v.w, 0.f);
                    *(float4*)(sm->u.ph2.tt2 + (lnbase + nn) * TTS + hoq * 4) = v;
                }
            }
            __syncthreads();
            {
                int i = tid & 31, cg = tid >> 5;
                ull a = pack2(cb2a, cb2b);
#pragma unroll 4
                for (int k = 0; k < Hh; k += 4) {
                    float4 tv4 = *(const float4*)(sm->u.ph2.tt2 + i * TTS + k);
                    const float* tp = (const float*)&tv4;
#pragma unroll
                    for (int kk = 0; kk < 4; kk++) {
                        ull tvv = pack2(tp[kk], tp[kk]);
                        ull cv = *(const ull*)(sm->cwbuf + (k + kk) * Cc + cg * 2);
                        a = ffma2(tvv, cv, a);
                    }
                }
                sm->u.ph2.lg[(P * 32 + i) * Cc + cg * 2 + 0] = lo2(a);
                sm->u.ph2.lg[(P * 32 + i) * Cc + cg * 2 + 1] = hi2(a);
            }
            __syncthreads();
        }

        if (tid < Nn) {
            float best = sm->u.ph2.lg[tid * Cc];
            int bi = 0;
            for (int c = 1; c < Cc; c++) {
                float v = sm->u.ph2.lg[tid * Cc + c];
                if (v > best) { best = v; bi = c; }
            }
            g_concepts[(size_t)bs * Nn + tid] = bi;
        }
        __syncthreads();
    }
}

// ====== kernel 4: per-sample clustering + pooling (R9 config, capture slot) ==
__global__ __launch_bounds__(192) void cluster_kernel(
    const float* __restrict__ xemb, const float* __restrict__ noise,
    float* __restrict__ outXnew, float* __restrict__ outAdj,
    float* __restrict__ outAssign, float invS) {
    __shared__ unsigned long long adjraw[Nn];
    __shared__ unsigned long long reach[Nn];
    __shared__ unsigned long long nodemask[Nn];
    __shared__ unsigned long long present;
    __shared__ int cp[Nn];
    __shared__ int assign[Nn];
    __shared__ int ncl;

    int bs = blockIdx.x;
    int b = bs & (Bq - 1);
    int tid = threadIdx.x;
    unsigned long long mb = g_maskbits[b];

    if (tid < Nn) {
        adjraw[tid] = g_adjbits[b * Nn + tid];
        cp[tid] = g_concepts[(size_t)bs * Nn + tid];
        nodemask[tid] = 0ull;
        if (tid == 0) { present = 0ull; ncl = 0; }
        NB64();
        int ci = cp[tid];
        unsigned long long cm = 0;
        for (int j = 0; j < Nn; j++)
            if (cp[j] == ci) cm |= 1ull << j;
        bool mi = (mb >> tid) & 1ull;
        unsigned long long e = mi ? (adjraw[tid] & cm & mb) : 0ull;
        reach[tid] = e | (1ull << tid);
        NB64();
        for (int it = 0; it < 6; it++) {
            unsigned long long cur = reach[tid];
            unsigned long long r = cur, t2 = cur;
            while (t2) {
                int j = __ffsll((long long)t2) - 1;
                r |= reach[j];
                t2 &= t2 - 1;
            }
            NB64();
            reach[tid] = r;
            NB64();
        }
        int root = 0;
        if (mi) {
            root = __ffsll((long long)reach[tid]) - 1;
            atomicOr(&present, 1ull << root);
        }
        NB64();
        int a = 0;
        if (mi) {
            unsigned long long pm = present & (0xFFFFFFFFFFFFFFFFull >> (63 - root));
            a = __popcll(pm);
            atomicOr(&nodemask[a - 1], 1ull << tid);
            atomicMax(&ncl, a);
        }
        assign[tid] = a;
        outAssign[(size_t)bs * Nn + tid] = (float)a;
    }
    __syncthreads();

    if (tid < Nn) {
        unsigned long long nm = nodemask[tid];
        if (nm) {
            unsigned long long ro = 0, t2 = nm;
            while (t2) {
                int j = __ffsll((long long)t2) - 1;
                ro |= adjraw[j];
                t2 &= t2 - 1;
            }
            float* arow = outAdj + (size_t)b * Nn * Nn + (size_t)tid * Nn;
            for (int c2 = 0; c2 < Nn; c2++)
                if (ro & nodemask[c2]) atomicAdd(&arow[c2], invS);
        }
        if (tid == 0) atomicMax(&g_maxcl[b], ncl);
    } else {
        int h = tid - 64;
        const float* xbp = xemb + (size_t)b * Nn * Hh + h;
        const float* nzp = noise + (size_t)bs * Nn * Hh + h;
        float* dst = outXnew + (size_t)b * (Nn * Hh) + h;
#pragma unroll 4
        for (int i = 0; i < Nn; i++) {
            int a = assign[i];
            float val = (xbp[i * Hh] + SIGMA * nzp[i * Hh]) * invS;
            if (a > 0) atomicAdd(&dst[(a - 1) * Hh], val);
        }
    }
}

// ====== kernel 5: mask_new ======
__global__ void finish_kernel(float* outMask) {
    int idx = blockIdx.x * blockDim.x + threadIdx.x;
    if (idx < Bq * Nn) {
        int b = idx >> 6, j = idx & 63;
        outMask[idx] = (j < g_maxcl[b]) ? 1.f : 0.f;
    }
}

// ---------------- host launcher ----------------
extern "C" void kernel_launch(void* const* d_in, const int* in_sizes, int n_in,
                              void* d_out, int out_size) {
    const float* x   = (const float*)d_in[0];
    const float* adj = (const float*)d_in[1];
    const void*  msk = d_in[2];
    const float* W1  = (const float*)d_in[3];
    const float* b1  = (const float*)d_in[4];
    const float* W2  = (const float*)d_in[5];
    const float* b2  = (const float*)d_in[6];
    const float* cW1 = (const float*)d_in[7];
    const float* cb1 = (const float*)d_in[8];
    const float* cW2 = (const float*)d_in[9];
    const float* cb2 = (const float*)d_in[10];
    const float* noise = (const float*)d_in[11];

    int S = in_sizes[11] / in_sizes[0];
    if (S <= 0) S = 1;
    if (S > SMAX) S = SMAX;

    float* out = (float*)d_out;
    size_t offAdj    = (size_t)Bq * Nn * Hh;
    size_t offAssign = offAdj + (size_t)Bq * Nn * Nn;
    size_t offXemb   = offAssign + (size_t)S * Bq * Nn;
    size_t offMask   = offXemb + (size_t)Bq * Nn * Hh;

    cudaFuncSetAttribute(gcn_all, cudaFuncAttributeMaxDynamicSharedMemorySize,
                         (int)sizeof(SmemG));
    cudaFuncSetAttribute(mlp_kernel, cudaFuncAttributeMaxDynamicSharedMemorySize,
                         (int)sizeof(SmemA));

    // #1: zero accumulators + reset job queue / maxcl
    zero_kernel<<<768, 256>>>(out, (int)offAssign);
    // #2: full GCN stack -> x_emb
    gcn_all<<<Bq, 256, sizeof(SmemG)>>>(x, adj, msk, W1, b1, W2, b2,
                                        out + offXemb);
    // #3: MLP+argmax, work-queue balanced, 4 blocks/SM full residency
    mlp_kernel<<<592, 256, sizeof(SmemA)>>>(
        out + offXemb, noise, cW1, cb1, cW2, cb2, S * Bq);
    // #4: per-sample clustering + pooling (ncu capture slot)
    cluster_kernel<<<S * Bq, 192>>>(out + offXemb, noise, out, out + offAdj,
                                    out + offAssign, 1.0f / (float)S);
    // #5: mask_new
    finish_kernel<<<(Bq * Nn + 255) / 256, 256>>>(out + offMask);
}